// round 2
// baseline (speedup 1.0000x reference)
#include <cuda_runtime.h>
#include <math.h>

#define NMAX   50000
#define DIN    64
#define FDIM   256
#define NH     4
#define MAXL1  4096                 // edges into node N-1
#define MAXT   (MAXL1 + 1)          // targets = N-1 + unique 1-hop srcs
#define MAXE1  32768                // edges into any target
#define MAXU   (MAXT + MAXE1)       // 2-hop frontier
#define MAXDEG 2048                 // per-target in-degree cap (smem list)

// ---------------- scratch (static device globals; no runtime allocation) ----
__device__ int   g_uslot[NMAX];
__device__ int   g_l1_src[MAXL1];
__device__ int   g_l1_us[MAXL1];
__device__ int   g_e1_dst[MAXE1];
__device__ int   g_e1_src[MAXE1];
__device__ int   g_e1_us[MAXE1];
__device__ int   g_ulist[MAXU];
__device__ int   g_cnt[4];          // 0=l1_cnt 1=tgt_cnt 2=u_cnt 3=e1_cnt
__device__ float g_h0[MAXU][FDIM];
__device__ float g_al0[MAXU][2*NH]; // [0..3]=al_src, [4..7]=al_dst
__device__ float g_feat1[MAXT][FDIM];
__device__ float g_h1[MAXT][FDIM];
__device__ float g_al1[MAXT][2*NH];
__device__ float g_mlp[DIN];

// ---------------- helpers ---------------------------------------------------
__device__ __forceinline__ float warp_sum(float v) {
    #pragma unroll
    for (int o = 16; o; o >>= 1) v += __shfl_xor_sync(0xffffffffu, v, o);
    return v;
}
__device__ __forceinline__ float warp_max(float v) {
    #pragma unroll
    for (int o = 16; o; o >>= 1) v = fmaxf(v, __shfl_xor_sync(0xffffffffu, v, o));
    return v;
}
__device__ __forceinline__ float lrelu(float x) { return x > 0.f ? x : 0.2f * x; }

// ---------------- stage 0: init ---------------------------------------------
__global__ void k_init(int N) {
    int stride = gridDim.x * blockDim.x;
    for (int i = blockIdx.x * blockDim.x + threadIdx.x; i < N; i += stride)
        g_uslot[i] = (i == N - 1) ? 0 : -1;
    if (blockIdx.x == 0 && threadIdx.x == 0) {
        g_cnt[0] = 0; g_cnt[1] = 1; g_cnt[2] = 1; g_cnt[3] = 0;
        g_ulist[0] = N - 1;       // uslot 0 = node N-1 (always a target)
    }
}

// ---------------- stage 1: collect in-edges of node N-1 ---------------------
__global__ void k_collect_l1(const int* __restrict__ src, const int* __restrict__ dst,
                             int E, int N) {
    int stride = gridDim.x * blockDim.x;
    for (int e = blockIdx.x * blockDim.x + threadIdx.x; e < E; e += stride) {
        if (dst[e] == N - 1) {
            int p = atomicAdd(&g_cnt[0], 1);
            if (p < MAXL1) g_l1_src[p] = src[e];
        }
    }
}

// ---------------- stage 2: claim U-slots for 1-hop srcs (targets) -----------
__global__ void k_claim_l1() {
    int n1 = min(g_cnt[0], MAXL1);
    int stride = gridDim.x * blockDim.x;
    for (int i = blockIdx.x * blockDim.x + threadIdx.x; i < n1; i += stride) {
        int s = g_l1_src[i];
        if (atomicCAS(&g_uslot[s], -1, -2) == -1) {
            int p = atomicAdd(&g_cnt[2], 1);
            g_uslot[s] = p;
            if (p < MAXU) g_ulist[p] = s;
        }
    }
}

// ---------------- stage 3: resolve l1 slots + collect edges into targets ----
__global__ void k_resolve_l1_collect_e1(const int* __restrict__ src,
                                        const int* __restrict__ dst, int E) {
    if (blockIdx.x == 0 && threadIdx.x == 0) g_cnt[1] = g_cnt[2]; // tgt_cnt snapshot
    int gtid = blockIdx.x * blockDim.x + threadIdx.x;
    int stride = gridDim.x * blockDim.x;
    int n1 = min(g_cnt[0], MAXL1);
    for (int i = gtid; i < n1; i += stride)
        g_l1_us[i] = g_uslot[g_l1_src[i]];
    for (int e = gtid; e < E; e += stride) {
        int t = g_uslot[dst[e]];          // >=0 iff dst is a target
        if (t >= 0) {
            int p = atomicAdd(&g_cnt[3], 1);
            if (p < MAXE1) { g_e1_dst[p] = t; g_e1_src[p] = src[e]; }
        }
    }
}

// ---------------- stage 4: claim U-slots for 2-hop srcs ---------------------
__global__ void k_claim_e1() {
    int n = min(g_cnt[3], MAXE1);
    int stride = gridDim.x * blockDim.x;
    for (int i = blockIdx.x * blockDim.x + threadIdx.x; i < n; i += stride) {
        int s = g_e1_src[i];
        if (atomicCAS(&g_uslot[s], -1, -2) == -1) {
            int p = atomicAdd(&g_cnt[2], 1);
            g_uslot[s] = p;
            if (p < MAXU) g_ulist[p] = s;
        }
    }
}

// ---------------- stage 5: resolve e1 srcs + h0 = emb[y]@W0 (+ al0) ---------
__global__ void k_h0(const int* __restrict__ y, const float* __restrict__ emb,
                     const float* __restrict__ W0, const float* __restrict__ a_s,
                     const float* __restrict__ a_d) {
    int e1n = min(g_cnt[3], MAXE1);
    int gtid = blockIdx.x * blockDim.x + threadIdx.x;
    int gstride = gridDim.x * blockDim.x;
    for (int i = gtid; i < e1n; i += gstride)
        g_e1_us[i] = g_uslot[g_e1_src[i]];

    __shared__ float xs[DIN];
    __shared__ float ws[8], wd[8];
    int ucnt = g_cnt[2];
    int tid = threadIdx.x, wid = tid >> 5, lane = tid & 31;
    for (int u = blockIdx.x; u < ucnt; u += gridDim.x) {
        int node = g_ulist[u];
        if (tid < DIN) xs[tid] = emb[(long long)y[node] * DIN + tid];
        __syncthreads();
        float acc = 0.f;
        #pragma unroll
        for (int d = 0; d < DIN; d++) acc += xs[d] * W0[d * FDIM + tid];
        g_h0[u][tid] = acc;
        float ps = warp_sum(acc * a_s[tid]);
        float pd = warp_sum(acc * a_d[tid]);
        if (lane == 0) { ws[wid] = ps; wd[wid] = pd; }
        __syncthreads();
        if (tid < 2 * NH) {
            int h = tid & 3;
            g_al0[u][tid] = (tid < NH) ? (ws[2*h] + ws[2*h+1]) : (wd[2*h] + wd[2*h+1]);
        }
        __syncthreads();
    }
}

// ---------------- stage 6: layer-0 GAT aggregation at targets ---------------
__global__ void k_agg0(const float* __restrict__ b0) {
    __shared__ int   eidx[MAXDEG];
    __shared__ int   ecnt;
    __shared__ float red[8][8];
    __shared__ float sm[NH], sden[NH], snorm;
    int tcnt = g_cnt[1];
    int e1n  = min(g_cnt[3], MAXE1);
    int tid = threadIdx.x, wid = tid >> 5, lane = tid & 31;
    for (int t = blockIdx.x; t < tcnt; t += gridDim.x) {
        if (tid == 0) ecnt = 0;
        __syncthreads();
        for (int i = tid; i < e1n; i += blockDim.x)
            if (g_e1_dst[i] == t) {
                int p = atomicAdd(&ecnt, 1);
                if (p < MAXDEG) eidx[p] = g_e1_us[i];
            }
        __syncthreads();
        int ne = min(ecnt, MAXDEG);          // + 1 implicit self-loop (usrc = t)

        float ald[NH];
        #pragma unroll
        for (int h = 0; h < NH; h++) ald[h] = g_al0[t][NH + h];

        // pass 1: per-head max
        float lm[NH];
        #pragma unroll
        for (int h = 0; h < NH; h++) lm[h] = -3.0e38f;
        for (int i = tid; i < ne + 1; i += blockDim.x) {
            int us = (i == ne) ? t : eidx[i];
            #pragma unroll
            for (int h = 0; h < NH; h++)
                lm[h] = fmaxf(lm[h], lrelu(g_al0[us][h] + ald[h]));
        }
        #pragma unroll
        for (int h = 0; h < NH; h++) {
            float v = warp_max(lm[h]);
            if (lane == 0) red[wid][h] = v;
        }
        __syncthreads();
        if (tid < NH) {
            float m = -3.0e38f;
            for (int w = 0; w < 8; w++) m = fmaxf(m, red[w][tid]);
            sm[tid] = m;
        }
        __syncthreads();

        // pass 2: per-head denominator
        float ld[NH] = {0.f, 0.f, 0.f, 0.f};
        for (int i = tid; i < ne + 1; i += blockDim.x) {
            int us = (i == ne) ? t : eidx[i];
            #pragma unroll
            for (int h = 0; h < NH; h++)
                ld[h] += expf(lrelu(g_al0[us][h] + ald[h]) - sm[h]);
        }
        #pragma unroll
        for (int h = 0; h < NH; h++) {
            float v = warp_sum(ld[h]);
            if (lane == 0) red[wid][h] = v;
        }
        __syncthreads();
        if (tid < NH) {
            float s = 0.f;
            for (int w = 0; w < 8; w++) s += red[w][tid];
            sden[tid] = s + 1e-16f;
        }
        __syncthreads();

        // pass 3: weighted feature sum per channel
        int c = tid, head = c >> 6;
        float m = sm[head], den = sden[head];
        float acc = 0.f;
        for (int i = 0; i <= ne; i++) {
            int us = (i == ne) ? t : eidx[i];
            float a = expf(lrelu(g_al0[us][head] + ald[head]) - m) / den;
            acc += a * g_h0[us][c];
        }
        acc += b0[c];
        acc = acc > 0.f ? acc : expm1f(acc);      // ELU
        float ss = warp_sum(acc * acc);
        if (lane == 0) red[wid][0] = ss;
        __syncthreads();
        if (tid == 0) {
            float s = 0.f;
            for (int w = 0; w < 8; w++) s += red[w][0];
            snorm = fmaxf(sqrtf(s), 1e-12f);
        }
        __syncthreads();
        g_feat1[t][c] = acc / snorm;
        __syncthreads();
    }
}

// ---------------- stage 7: h1 = feat1 @ W1 (+ al1) at targets ---------------
__global__ void k_h1(const float* __restrict__ W1, const float* __restrict__ a_s,
                     const float* __restrict__ a_d) {
    __shared__ float fs[FDIM];
    __shared__ float ws[8], wd[8];
    int tcnt = g_cnt[1];
    int tid = threadIdx.x, wid = tid >> 5, lane = tid & 31;
    for (int t = blockIdx.x; t < tcnt; t += gridDim.x) {
        fs[tid] = g_feat1[t][tid];
        __syncthreads();
        float acc = 0.f;
        #pragma unroll 8
        for (int k = 0; k < FDIM; k++) acc += fs[k] * W1[k * FDIM + tid];
        g_h1[t][tid] = acc;
        float ps = warp_sum(acc * a_s[tid]);
        float pd = warp_sum(acc * a_d[tid]);
        if (lane == 0) { ws[wid] = ps; wd[wid] = pd; }
        __syncthreads();
        if (tid < 2 * NH) {
            int h = tid & 3;
            g_al1[t][tid] = (tid < NH) ? (ws[2*h] + ws[2*h+1]) : (wd[2*h] + wd[2*h+1]);
        }
        __syncthreads();
    }
}

// ---------------- stage 8: layer-1 aggregation at N-1 + ctx MLP -------------
__global__ void k_final(const float* __restrict__ b1, const float* __restrict__ pw1,
                        const float* __restrict__ pb1) {
    __shared__ float red[8][8];
    __shared__ float sm[NH], sden[NH], snorm;
    __shared__ float ctx_s[FDIM];
    int n1 = min(g_cnt[0], MAXL1);
    int tid = threadIdx.x, wid = tid >> 5, lane = tid & 31;

    float ald[NH];
    #pragma unroll
    for (int h = 0; h < NH; h++) ald[h] = g_al1[0][NH + h];

    float lm[NH];
    #pragma unroll
    for (int h = 0; h < NH; h++) lm[h] = -3.0e38f;
    for (int i = tid; i < n1 + 1; i += blockDim.x) {
        int us = (i == n1) ? 0 : g_l1_us[i];
        #pragma unroll
        for (int h = 0; h < NH; h++)
            lm[h] = fmaxf(lm[h], lrelu(g_al1[us][h] + ald[h]));
    }
    #pragma unroll
    for (int h = 0; h < NH; h++) {
        float v = warp_max(lm[h]);
        if (lane == 0) red[wid][h] = v;
    }
    __syncthreads();
    if (tid < NH) {
        float m = -3.0e38f;
        for (int w = 0; w < 8; w++) m = fmaxf(m, red[w][tid]);
        sm[tid] = m;
    }
    __syncthreads();

    float ld[NH] = {0.f, 0.f, 0.f, 0.f};
    for (int i = tid; i < n1 + 1; i += blockDim.x) {
        int us = (i == n1) ? 0 : g_l1_us[i];
        #pragma unroll
        for (int h = 0; h < NH; h++)
            ld[h] += expf(lrelu(g_al1[us][h] + ald[h]) - sm[h]);
    }
    #pragma unroll
    for (int h = 0; h < NH; h++) {
        float v = warp_sum(ld[h]);
        if (lane == 0) red[wid][h] = v;
    }
    __syncthreads();
    if (tid < NH) {
        float s = 0.f;
        for (int w = 0; w < 8; w++) s += red[w][tid];
        sden[tid] = s + 1e-16f;
    }
    __syncthreads();

    int c = tid, head = c >> 6;
    float m = sm[head], den = sden[head];
    float acc = 0.f;
    for (int i = 0; i <= n1; i++) {
        int us = (i == n1) ? 0 : g_l1_us[i];
        float a = expf(lrelu(g_al1[us][head] + ald[head]) - m) / den;
        acc += a * g_h1[us][c];
    }
    acc += b1[c];
    acc = acc > 0.f ? acc : expm1f(acc);
    float ss = warp_sum(acc * acc);
    if (lane == 0) red[wid][0] = ss;
    __syncthreads();
    if (tid == 0) {
        float s = 0.f;
        for (int w = 0; w < 8; w++) s += red[w][0];
        snorm = fmaxf(sqrtf(s), 1e-12f);
    }
    __syncthreads();
    ctx_s[c] = acc / snorm;
    __syncthreads();

    // ctx @ pw1 + pb1, relu  -> g_mlp[64]
    if (tid < DIN) {
        float a = pb1[tid];
        #pragma unroll 8
        for (int k = 0; k < FDIM; k++) a += ctx_s[k] * pw1[k * DIN + tid];
        g_mlp[tid] = fmaxf(a, 0.f);
    }
}

// ---------------- stage 9: out = mlp @ pw2 + pb2 ----------------------------
__global__ void k_out(const float* __restrict__ pw2, const float* __restrict__ pb2,
                      float* __restrict__ out, int V) {
    __shared__ float m[DIN];
    if (threadIdx.x < DIN) m[threadIdx.x] = g_mlp[threadIdx.x];
    __syncthreads();
    int gtid = blockIdx.x * blockDim.x + threadIdx.x;
    int stride = gridDim.x * blockDim.x;
    if ((V & 3) == 0) {
        int V4 = V >> 2;
        const float4* pw24 = (const float4*)pw2;
        const float4* pb24 = (const float4*)pb2;
        float4* out4 = (float4*)out;
        for (int v = gtid; v < V4; v += stride) {
            float4 acc = pb24[v];
            #pragma unroll
            for (int j = 0; j < DIN; j++) {
                float w = m[j];
                float4 p = pw24[(size_t)j * V4 + v];
                acc.x += w * p.x; acc.y += w * p.y;
                acc.z += w * p.z; acc.w += w * p.w;
            }
            out4[v] = acc;
        }
    } else {
        for (int v = gtid; v < V; v += stride) {
            float acc = pb2[v];
            for (int j = 0; j < DIN; j++) acc += m[j] * pw2[(size_t)j * V + v];
            out[v] = acc;
        }
    }
}

// ---------------- launcher ---------------------------------------------------
extern "C" void kernel_launch(void* const* d_in, const int* in_sizes, int n_in,
                              void* d_out, int out_size) {
    const int*   y   = (const int*)  d_in[0];
    const int*   ei  = (const int*)  d_in[1];
    const float* emb = (const float*)d_in[2];
    const float* W0  = (const float*)d_in[3];
    const float* as0 = (const float*)d_in[4];
    const float* ad0 = (const float*)d_in[5];
    const float* b0  = (const float*)d_in[6];
    const float* W1  = (const float*)d_in[7];
    const float* as1 = (const float*)d_in[8];
    const float* ad1 = (const float*)d_in[9];
    const float* b1  = (const float*)d_in[10];
    const float* pw1 = (const float*)d_in[11];
    const float* pb1 = (const float*)d_in[12];
    const float* pw2 = (const float*)d_in[13];
    const float* pb2 = (const float*)d_in[14];
    float* out = (float*)d_out;

    int N = in_sizes[0];
    int E = in_sizes[1] / 2;
    int V = out_size;
    const int* srcp = ei;
    const int* dstp = ei + E;

    k_init<<<128, 256>>>(N);
    k_collect_l1<<<512, 256>>>(srcp, dstp, E, N);
    k_claim_l1<<<16, 256>>>();
    k_resolve_l1_collect_e1<<<512, 256>>>(srcp, dstp, E);
    k_claim_e1<<<64, 256>>>();
    k_h0<<<512, 256>>>(y, emb, W0, as0, ad0);
    k_agg0<<<64, 256>>>(b0);
    k_h1<<<64, 256>>>(W1, as1, ad1);
    k_final<<<1, 256>>>(b1, pw1, pb1);
    k_out<<<296, 256>>>(pw2, pb2, out, V);
}

// round 3
// speedup vs baseline: 1.3538x; 1.3538x over previous
#include <cuda_runtime.h>
#include <math.h>

#define NMAX   50000
#define DIN    64
#define FDIM   256
#define NH     4
#define MAXL1  4096                 // edges into node N-1
#define MAXT   (MAXL1 + 1)
#define MAXE1  32768                // edges into any target
#define MAXU   (MAXT + MAXE1)
#define MAXDEG 2048
#define NBW    1568                 // bitmap words (>= NMAX/32)

// ---------------- scratch (static device globals) ---------------------------
__device__ int   g_uslot[NMAX];
__device__ unsigned g_tbit[NBW];    // target-membership bitmap
__device__ int   g_l1_src[MAXL1];
__device__ int   g_l1_us[MAXL1];
__device__ int   g_e1_dstn[MAXE1];  // dst NODE id (resolved to slot in prep2)
__device__ int   g_e1_dst[MAXE1];   // dst target slot
__device__ int   g_e1_src[MAXE1];
__device__ int   g_e1_us[MAXE1];
__device__ int   g_ulist[MAXU];
__device__ int   g_cnt[4];          // 0=l1 1=tgt 2=u 3=e1
__device__ float g_h0[MAXU][FDIM];
__device__ float g_al0[MAXU][2*NH];
__device__ float g_h1[MAXT][FDIM];
__device__ float g_al1[MAXT][2*NH];
__device__ float g_mlp[DIN];

// ---------------- helpers ---------------------------------------------------
__device__ __forceinline__ float warp_sum(float v) {
    #pragma unroll
    for (int o = 16; o; o >>= 1) v += __shfl_xor_sync(0xffffffffu, v, o);
    return v;
}
__device__ __forceinline__ float warp_max(float v) {
    #pragma unroll
    for (int o = 16; o; o >>= 1) v = fmaxf(v, __shfl_xor_sync(0xffffffffu, v, o));
    return v;
}
__device__ __forceinline__ float lrelu(float x) { return x > 0.f ? x : 0.2f * x; }

// ---------------- 1: init ---------------------------------------------------
__global__ void k_init(int N) {
    int gtid = blockIdx.x * blockDim.x + threadIdx.x;
    int stride = gridDim.x * blockDim.x;
    for (int i = gtid; i < N; i += stride)
        g_uslot[i] = (i == N - 1) ? 0 : -1;
    for (int i = gtid; i < NBW; i += stride)
        g_tbit[i] = (i == (N - 1) >> 5) ? (1u << ((N - 1) & 31)) : 0u;
    if (gtid == 0) {
        g_cnt[0] = 0; g_cnt[1] = 1; g_cnt[2] = 1; g_cnt[3] = 0;
        g_ulist[0] = N - 1;
    }
}

// ---------------- 2: scan edges for dst == N-1 (vectorized) -----------------
__global__ void k_scan1(const int4* __restrict__ dst4, const int* __restrict__ dst,
                        const int* __restrict__ src, int E4, int E, int N) {
    int gtid = blockIdx.x * blockDim.x + threadIdx.x;
    int stride = gridDim.x * blockDim.x;
    int tgt = N - 1;
    for (int i = gtid; i < E4; i += stride) {
        int4 d = dst4[i];
        int base = i << 2;
        if (d.x == tgt) { int p = atomicAdd(&g_cnt[0], 1); if (p < MAXL1) g_l1_src[p] = src[base]; }
        if (d.y == tgt) { int p = atomicAdd(&g_cnt[0], 1); if (p < MAXL1) g_l1_src[p] = src[base + 1]; }
        if (d.z == tgt) { int p = atomicAdd(&g_cnt[0], 1); if (p < MAXL1) g_l1_src[p] = src[base + 2]; }
        if (d.w == tgt) { int p = atomicAdd(&g_cnt[0], 1); if (p < MAXL1) g_l1_src[p] = src[base + 3]; }
    }
    // remainder
    for (int e = (E4 << 2) + gtid; e < E; e += stride)
        if (dst[e] == tgt) { int p = atomicAdd(&g_cnt[0], 1); if (p < MAXL1) g_l1_src[p] = src[e]; }
}

// ---------------- 3: single-block claim l1 targets + resolve + bitmap -------
__global__ void k_prep1() {
    int n1 = min(g_cnt[0], MAXL1);
    int tid = threadIdx.x;
    for (int i = tid; i < n1; i += blockDim.x) {
        int s = g_l1_src[i];
        if (atomicCAS(&g_uslot[s], -1, -2) == -1) {
            int p = atomicAdd(&g_cnt[2], 1);
            g_uslot[s] = p;
            if (p < MAXU) g_ulist[p] = s;
            atomicOr(&g_tbit[s >> 5], 1u << (s & 31));
        }
    }
    __syncthreads();
    if (tid == 0) g_cnt[1] = g_cnt[2];
    for (int i = tid; i < n1; i += blockDim.x)
        g_l1_us[i] = g_uslot[g_l1_src[i]];
}

// ---------------- 4: scan edges for dst in target set (bitmap, vectorized) --
__global__ void k_scan2(const int4* __restrict__ dst4, const int* __restrict__ dst,
                        const int* __restrict__ src, int E4, int E) {
    int gtid = blockIdx.x * blockDim.x + threadIdx.x;
    int stride = gridDim.x * blockDim.x;
    for (int i = gtid; i < E4; i += stride) {
        int4 d = dst4[i];
        int base = i << 2;
        unsigned wx = g_tbit[d.x >> 5], wy = g_tbit[d.y >> 5];
        unsigned wz = g_tbit[d.z >> 5], ww = g_tbit[d.w >> 5];
        if ((wx >> (d.x & 31)) & 1u) { int p = atomicAdd(&g_cnt[3], 1); if (p < MAXE1) { g_e1_dstn[p] = d.x; g_e1_src[p] = src[base]; } }
        if ((wy >> (d.y & 31)) & 1u) { int p = atomicAdd(&g_cnt[3], 1); if (p < MAXE1) { g_e1_dstn[p] = d.y; g_e1_src[p] = src[base + 1]; } }
        if ((wz >> (d.z & 31)) & 1u) { int p = atomicAdd(&g_cnt[3], 1); if (p < MAXE1) { g_e1_dstn[p] = d.z; g_e1_src[p] = src[base + 2]; } }
        if ((ww >> (d.w & 31)) & 1u) { int p = atomicAdd(&g_cnt[3], 1); if (p < MAXE1) { g_e1_dstn[p] = d.w; g_e1_src[p] = src[base + 3]; } }
    }
    for (int e = (E4 << 2) + gtid; e < E; e += stride) {
        int d = dst[e];
        if ((g_tbit[d >> 5] >> (d & 31)) & 1u) {
            int p = atomicAdd(&g_cnt[3], 1);
            if (p < MAXE1) { g_e1_dstn[p] = d; g_e1_src[p] = src[e]; }
        }
    }
}

// ---------------- 5: single-block claim 2-hop srcs + resolve ----------------
__global__ void k_prep2() {
    int n = min(g_cnt[3], MAXE1);
    int tid = threadIdx.x;
    for (int i = tid; i < n; i += blockDim.x) {
        int s = g_e1_src[i];
        if (atomicCAS(&g_uslot[s], -1, -2) == -1) {
            int p = atomicAdd(&g_cnt[2], 1);
            g_uslot[s] = p;
            if (p < MAXU) g_ulist[p] = s;
        }
    }
    __syncthreads();
    for (int i = tid; i < n; i += blockDim.x) {
        g_e1_us[i]  = g_uslot[g_e1_src[i]];
        g_e1_dst[i] = g_uslot[g_e1_dstn[i]];
    }
}

// ---------------- 6: h0 = emb[y]@W0 (+ al0) over frontier -------------------
__global__ void k_h0(const int* __restrict__ y, const float* __restrict__ emb,
                     const float* __restrict__ W0, const float* __restrict__ a_s,
                     const float* __restrict__ a_d) {
    __shared__ float xs[DIN];
    __shared__ float ws[8], wd[8];
    int ucnt = g_cnt[2];
    int tid = threadIdx.x, wid = tid >> 5, lane = tid & 31;
    for (int u = blockIdx.x; u < ucnt; u += gridDim.x) {
        int node = g_ulist[u];
        if (tid < DIN) xs[tid] = emb[(long long)y[node] * DIN + tid];
        __syncthreads();
        float acc = 0.f;
        #pragma unroll
        for (int d = 0; d < DIN; d++) acc += xs[d] * W0[d * FDIM + tid];
        g_h0[u][tid] = acc;
        float ps = warp_sum(acc * a_s[tid]);
        float pd = warp_sum(acc * a_d[tid]);
        if (lane == 0) { ws[wid] = ps; wd[wid] = pd; }
        __syncthreads();
        if (tid < 2 * NH) {
            int h = tid & 3;
            g_al0[u][tid] = (tid < NH) ? (ws[2*h] + ws[2*h+1]) : (wd[2*h] + wd[2*h+1]);
        }
        __syncthreads();
    }
}

// ---------------- 7: layer-0 aggregation + layer-1 transform (fused) --------
__global__ void k_agg01(const float* __restrict__ b0, const float* __restrict__ W1,
                        const float* __restrict__ a_s, const float* __restrict__ a_d) {
    __shared__ int   eidx[MAXDEG];
    __shared__ int   ecnt;
    __shared__ float red[8][8];
    __shared__ float sm[NH], sden[NH], snorm;
    __shared__ float fs[FDIM];
    int tcnt = g_cnt[1];
    int e1n  = min(g_cnt[3], MAXE1);
    int tid = threadIdx.x, wid = tid >> 5, lane = tid & 31;
    for (int t = blockIdx.x; t < tcnt; t += gridDim.x) {
        if (tid == 0) ecnt = 0;
        __syncthreads();
        for (int i = tid; i < e1n; i += blockDim.x)
            if (g_e1_dst[i] == t) {
                int p = atomicAdd(&ecnt, 1);
                if (p < MAXDEG) eidx[p] = g_e1_us[i];
            }
        __syncthreads();
        int ne = min(ecnt, MAXDEG);          // + 1 implicit self-loop

        float ald[NH];
        #pragma unroll
        for (int h = 0; h < NH; h++) ald[h] = g_al0[t][NH + h];

        // pass 1: per-head max
        float lm[NH];
        #pragma unroll
        for (int h = 0; h < NH; h++) lm[h] = -3.0e38f;
        for (int i = tid; i < ne + 1; i += blockDim.x) {
            int us = (i == ne) ? t : eidx[i];
            #pragma unroll
            for (int h = 0; h < NH; h++)
                lm[h] = fmaxf(lm[h], lrelu(g_al0[us][h] + ald[h]));
        }
        #pragma unroll
        for (int h = 0; h < NH; h++) {
            float v = warp_max(lm[h]);
            if (lane == 0) red[wid][h] = v;
        }
        __syncthreads();
        if (tid < NH) {
            float m = -3.0e38f;
            for (int w = 0; w < 8; w++) m = fmaxf(m, red[w][tid]);
            sm[tid] = m;
        }
        __syncthreads();

        // pass 2: denominators
        float ld[NH] = {0.f, 0.f, 0.f, 0.f};
        for (int i = tid; i < ne + 1; i += blockDim.x) {
            int us = (i == ne) ? t : eidx[i];
            #pragma unroll
            for (int h = 0; h < NH; h++)
                ld[h] += expf(lrelu(g_al0[us][h] + ald[h]) - sm[h]);
        }
        #pragma unroll
        for (int h = 0; h < NH; h++) {
            float v = warp_sum(ld[h]);
            if (lane == 0) red[wid][h] = v;
        }
        __syncthreads();
        if (tid < NH) {
            float s = 0.f;
            for (int w = 0; w < 8; w++) s += red[w][tid];
            sden[tid] = s + 1e-16f;
        }
        __syncthreads();

        // pass 3: weighted feature sum
        int c = tid, head = c >> 6;
        float m = sm[head], den = sden[head];
        float acc = 0.f;
        for (int i = 0; i <= ne; i++) {
            int us = (i == ne) ? t : eidx[i];
            float a = expf(lrelu(g_al0[us][head] + ald[head]) - m) / den;
            acc += a * g_h0[us][c];
        }
        acc += b0[c];
        acc = acc > 0.f ? acc : expm1f(acc);      // ELU
        float ss = warp_sum(acc * acc);
        if (lane == 0) red[wid][0] = ss;
        __syncthreads();
        if (tid == 0) {
            float s = 0.f;
            for (int w = 0; w < 8; w++) s += red[w][0];
            snorm = fmaxf(sqrtf(s), 1e-12f);
        }
        __syncthreads();
        fs[c] = acc / snorm;                 // feat1 stays in smem
        __syncthreads();

        // fused layer-1 transform: h1 = fs @ W1  (+ al1)
        float acc1 = 0.f;
        #pragma unroll 8
        for (int k = 0; k < FDIM; k++) acc1 += fs[k] * W1[k * FDIM + tid];
        g_h1[t][tid] = acc1;
        float ps = warp_sum(acc1 * a_s[tid]);
        float pd = warp_sum(acc1 * a_d[tid]);
        if (lane == 0) { red[wid][0] = ps; red[wid][1] = pd; }
        __syncthreads();
        if (tid < 2 * NH) {
            int h = tid & 3;
            g_al1[t][tid] = (tid < NH) ? (red[2*h][0] + red[2*h+1][0])
                                       : (red[2*h][1] + red[2*h+1][1]);
        }
        __syncthreads();
    }
}

// ---------------- 8: layer-1 aggregation at N-1 + ctx MLP -------------------
__global__ void k_final(const float* __restrict__ b1, const float* __restrict__ pw1,
                        const float* __restrict__ pb1) {
    __shared__ float red[8][8];
    __shared__ float sm[NH], sden[NH], snorm;
    __shared__ float ctx_s[FDIM];
    __shared__ float part[4][DIN];
    int n1 = min(g_cnt[0], MAXL1);
    int tid = threadIdx.x, wid = tid >> 5, lane = tid & 31;

    float ald[NH];
    #pragma unroll
    for (int h = 0; h < NH; h++) ald[h] = g_al1[0][NH + h];

    float lm[NH];
    #pragma unroll
    for (int h = 0; h < NH; h++) lm[h] = -3.0e38f;
    for (int i = tid; i < n1 + 1; i += blockDim.x) {
        int us = (i == n1) ? 0 : g_l1_us[i];
        #pragma unroll
        for (int h = 0; h < NH; h++)
            lm[h] = fmaxf(lm[h], lrelu(g_al1[us][h] + ald[h]));
    }
    #pragma unroll
    for (int h = 0; h < NH; h++) {
        float v = warp_max(lm[h]);
        if (lane == 0) red[wid][h] = v;
    }
    __syncthreads();
    if (tid < NH) {
        float m = -3.0e38f;
        for (int w = 0; w < 8; w++) m = fmaxf(m, red[w][tid]);
        sm[tid] = m;
    }
    __syncthreads();

    float ld[NH] = {0.f, 0.f, 0.f, 0.f};
    for (int i = tid; i < n1 + 1; i += blockDim.x) {
        int us = (i == n1) ? 0 : g_l1_us[i];
        #pragma unroll
        for (int h = 0; h < NH; h++)
            ld[h] += expf(lrelu(g_al1[us][h] + ald[h]) - sm[h]);
    }
    #pragma unroll
    for (int h = 0; h < NH; h++) {
        float v = warp_sum(ld[h]);
        if (lane == 0) red[wid][h] = v;
    }
    __syncthreads();
    if (tid < NH) {
        float s = 0.f;
        for (int w = 0; w < 8; w++) s += red[w][tid];
        sden[tid] = s + 1e-16f;
    }
    __syncthreads();

    int c = tid, head = c >> 6;
    float m = sm[head], den = sden[head];
    float acc = 0.f;
    for (int i = 0; i <= n1; i++) {
        int us = (i == n1) ? 0 : g_l1_us[i];
        float a = expf(lrelu(g_al1[us][head] + ald[head]) - m) / den;
        acc += a * g_h1[us][c];
    }
    acc += b1[c];
    acc = acc > 0.f ? acc : expm1f(acc);
    float ss = warp_sum(acc * acc);
    if (lane == 0) red[wid][0] = ss;
    __syncthreads();
    if (tid == 0) {
        float s = 0.f;
        for (int w = 0; w < 8; w++) s += red[w][0];
        snorm = fmaxf(sqrtf(s), 1e-12f);
    }
    __syncthreads();
    ctx_s[c] = acc / snorm;
    __syncthreads();

    // ctx @ pw1 + pb1, relu (parallel over all 256 threads: 4 k-slices x 64 cols)
    {
        int col = tid & 63, seg = tid >> 6;       // seg in 0..3
        float a = 0.f;
        #pragma unroll
        for (int k = seg * 64; k < seg * 64 + 64; k++)
            a += ctx_s[k] * pw1[k * DIN + col];
        part[seg][col] = a;
    }
    __syncthreads();
    if (tid < DIN) {
        float a = pb1[tid] + part[0][tid] + part[1][tid] + part[2][tid] + part[3][tid];
        g_mlp[tid] = fmaxf(a, 0.f);
    }
}

// ---------------- 9: out = mlp @ pw2 + pb2 ----------------------------------
__global__ void k_out(const float* __restrict__ pw2, const float* __restrict__ pb2,
                      float* __restrict__ out, int V) {
    __shared__ float m[DIN];
    if (threadIdx.x < DIN) m[threadIdx.x] = g_mlp[threadIdx.x];
    __syncthreads();
    int gtid = blockIdx.x * blockDim.x + threadIdx.x;
    int stride = gridDim.x * blockDim.x;
    if ((V & 3) == 0) {
        int V4 = V >> 2;
        const float4* pw24 = (const float4*)pw2;
        const float4* pb24 = (const float4*)pb2;
        float4* out4 = (float4*)out;
        for (int v = gtid; v < V4; v += stride) {
            float4 acc = pb24[v];
            #pragma unroll
            for (int j = 0; j < DIN; j++) {
                float w = m[j];
                float4 p = pw24[(size_t)j * V4 + v];
                acc.x += w * p.x; acc.y += w * p.y;
                acc.z += w * p.z; acc.w += w * p.w;
            }
            out4[v] = acc;
        }
    } else {
        for (int v = gtid; v < V; v += stride) {
            float acc = pb2[v];
            for (int j = 0; j < DIN; j++) acc += m[j] * pw2[(size_t)j * V + v];
            out[v] = acc;
        }
    }
}

// ---------------- launcher ---------------------------------------------------
extern "C" void kernel_launch(void* const* d_in, const int* in_sizes, int n_in,
                              void* d_out, int out_size) {
    const int*   y   = (const int*)  d_in[0];
    const int*   ei  = (const int*)  d_in[1];
    const float* emb = (const float*)d_in[2];
    const float* W0  = (const float*)d_in[3];
    const float* as0 = (const float*)d_in[4];
    const float* ad0 = (const float*)d_in[5];
    const float* b0  = (const float*)d_in[6];
    const float* W1  = (const float*)d_in[7];
    const float* as1 = (const float*)d_in[8];
    const float* ad1 = (const float*)d_in[9];
    const float* b1  = (const float*)d_in[10];
    const float* pw1 = (const float*)d_in[11];
    const float* pb1 = (const float*)d_in[12];
    const float* pw2 = (const float*)d_in[13];
    const float* pb2 = (const float*)d_in[14];
    float* out = (float*)d_out;

    int N = in_sizes[0];
    int E = in_sizes[1] / 2;
    int V = out_size;
    const int* srcp = ei;
    const int* dstp = ei + E;
    int E4 = (((size_t)dstp & 15) == 0) ? (E >> 2) : 0;   // int4 path only if aligned
    const int4* dst4 = (const int4*)dstp;

    k_init<<<196, 256>>>(N);
    k_scan1<<<592, 256>>>(dst4, dstp, srcp, E4, E, N);
    k_prep1<<<1, 256>>>();
    k_scan2<<<592, 256>>>(dst4, dstp, srcp, E4, E);
    k_prep2<<<1, 256>>>();
    k_h0<<<320, 256>>>(y, emb, W0, as0, ad0);
    k_agg01<<<32, 256>>>(b0, W1, as1, ad1);
    k_final<<<1, 256>>>(b1, pw1, pb1);

    int V4 = V >> 2;
    int gout = (V & 3) == 0 ? (V4 + 255) / 256 : (V + 255) / 256;
    if (gout < 1) gout = 1;
    if (gout > 1024) gout = 1024;
    k_out<<<gout, 256>>>(pw2, pb2, out, V);
}